// round 16
// baseline (speedup 1.0000x reference)
#include <cuda_runtime.h>

#define Bsz 256
#define Csz 128
#define Nsz 64
#define Psz 16
#define Qsz 48
#define TB 128
#define WPB 4
#define SWEEPS_W 6
#define SWEEPS_NV 4
#define SWEEPS_D 5
#define S17 17
#define JTOL 1e-13f
#define FULLM 0xffffffffu

// ---------------- device scratch (static, no allocations) ----------------
__device__ alignas(16) float gXlog[(size_t)Bsz * Csz * Nsz * Psz]; // 128MB
__device__ float gTheta[Bsz * Csz];
__device__ alignas(16) float gBmF[Csz * Qsz * Psz];
__device__ alignas(16) float gGinvCF[Csz * Psz * Psz];
__device__ alignas(16) float gGinvBF[Psz * Psz];
__device__ float gFactorF[Csz];

// tournament pair k at round r (p > q)
__device__ __forceinline__ void pqk(int k, int r, int& p, int& q) {
    if (k == 0) { p = 15; q = r; }
    else {
        p = r + k; if (p >= 15) p -= 15;
        q = r + 15 - k; if (q >= 15) q -= 15;
    }
    if (p < q) { int t = p; p = q; q = t; }
}

// ================= warp-level fp32 Jacobi: fused 2x2-block rounds =================
__device__ __forceinline__ void jacobi_warp(float* W, float* V, int lane,
                                            int sweeps, bool wantV) {
    const int jv = lane >> 2;
    const int b4v = (lane & 3) * 4;
    const int i0 = lane >> 3;
    const int jb = lane & 7;
    for (int sweep = 0; sweep < sweeps; ++sweep) {
        if (sweep >= sweeps - 2) {
            __syncwarp();
            float acc = 0.f;
            #pragma unroll
            for (int ii = 0; ii < 8; ++ii) {
                int i = lane + 32 * ii;
                int r = i >> 4, cc = i & 15;
                float v = (r < cc) ? W[r * S17 + cc] : 0.f;
                acc = __fmaf_rn(v, v, acc);
            }
            #pragma unroll
            for (int off = 16; off; off >>= 1)
                acc += __shfl_xor_sync(FULLM, acc, off);
            if (acc < JTOL) break;
        }
        for (int r = 0; r < 15; ++r) {
            __syncwarp();
            float cv = 1.f, sv = 0.f;
            if (lane < 8) {
                int p, q; pqk(lane, r, p, q);
                float app = W[p * S17 + p], aqq = W[q * S17 + q], apq = W[p * S17 + q];
                if (fabsf(apq) > 1e-37f) {
                    float tau = (aqq - app) / (2.f * apq);
                    float tt = copysignf(1.f, tau) / (fabsf(tau) + sqrtf(1.f + tau * tau));
                    cv = rsqrtf(1.f + tt * tt);
                    sv = tt * cv;
                }
            }
            float ci0 = __shfl_sync(FULLM, cv, i0),     si0 = __shfl_sync(FULLM, sv, i0);
            float ci1 = __shfl_sync(FULLM, cv, i0 + 4), si1 = __shfl_sync(FULLM, sv, i0 + 4);
            float cjb = __shfl_sync(FULLM, cv, jb),     sjb = __shfl_sync(FULLM, sv, jb);
            int pj, qj; pqk(jb, r, pj, qj);
            {
                int pi, qi; pqk(i0, r, pi, qi);
                float wpp = W[pi * S17 + pj], wpq = W[pi * S17 + qj];
                float wqp = W[qi * S17 + pj], wqq = W[qi * S17 + qj];
                float rpp = ci0 * wpp - si0 * wqp;
                float rpq = ci0 * wpq - si0 * wqq;
                float rqp = si0 * wpp + ci0 * wqp;
                float rqq = si0 * wpq + ci0 * wqq;
                W[pi * S17 + pj] = cjb * rpp - sjb * rpq;
                W[pi * S17 + qj] = sjb * rpp + cjb * rpq;
                W[qi * S17 + pj] = cjb * rqp - sjb * rqq;
                W[qi * S17 + qj] = sjb * rqp + cjb * rqq;
            }
            {
                int pi, qi; pqk(i0 + 4, r, pi, qi);
                float wpp = W[pi * S17 + pj], wpq = W[pi * S17 + qj];
                float wqp = W[qi * S17 + pj], wqq = W[qi * S17 + qj];
                float rpp = ci1 * wpp - si1 * wqp;
                float rpq = ci1 * wpq - si1 * wqq;
                float rqp = si1 * wpp + ci1 * wqp;
                float rqq = si1 * wpq + ci1 * wqq;
                W[pi * S17 + pj] = cjb * rpp - sjb * rpq;
                W[pi * S17 + qj] = sjb * rpp + cjb * rpq;
                W[qi * S17 + pj] = cjb * rqp - sjb * rqq;
                W[qi * S17 + qj] = sjb * rqp + cjb * rqq;
            }
            if (wantV) {
                float cjv = __shfl_sync(FULLM, cv, jv), sjv = __shfl_sync(FULLM, sv, jv);
                int pv, qv; pqk(jv, r, pv, qv);
                #pragma unroll
                for (int k = 0; k < 4; ++k) {
                    int row = b4v + k;
                    float vp = V[row * S17 + pv], vq = V[row * S17 + qv];
                    V[row * S17 + pv] = cjv * vp - sjv * vq;
                    V[row * S17 + qv] = sjv * vp + cjv * vq;
                }
            }
        }
    }
    __syncwarp();
}

// ================= block-level fp64 helpers (k2) =================
__device__ void jacobi16d(double* W, double* V, double* cs) {
    const int t = threadIdx.x;
    for (int i = t; i < 256; i += TB) V[i] = ((i >> 4) == (i & 15)) ? 1.0 : 0.0;
    __syncthreads();
    const int pr = t >> 4, el = t & 15;
    for (int sweep = 0; sweep < SWEEPS_D; ++sweep) {
        for (int r = 0; r < 15; ++r) {
            int p, q;
            if (pr == 0) { p = 15; q = r; }
            else { p = (r + pr) % 15; q = (r + 15 - pr) % 15; }
            if (p < q) { int tmp = p; p = q; q = tmp; }
            if (el == 0) {
                double app = W[p * 16 + p], aqq = W[q * 16 + q], apq = W[p * 16 + q];
                double c = 1.0, s = 0.0;
                if (fabs(apq) > 1e-300) {
                    double tau = (aqq - app) / (2.0 * apq);
                    double tt = copysign(1.0, tau) / (fabs(tau) + sqrt(1.0 + tau * tau));
                    c = rsqrt(1.0 + tt * tt);
                    s = tt * c;
                }
                cs[pr] = c; cs[8 + pr] = s;
            }
            __syncthreads();
            double c = cs[pr], s = cs[8 + pr];
            double wp = W[p * 16 + el], wq = W[q * 16 + el];
            W[p * 16 + el] = c * wp - s * wq;
            W[q * 16 + el] = s * wp + c * wq;
            __syncthreads();
            double xp = W[el * 16 + p], xq = W[el * 16 + q];
            W[el * 16 + p] = c * xp - s * xq;
            W[el * 16 + q] = s * xp + c * xq;
            double vp = V[el * 16 + p], vq = V[el * 16 + q];
            V[el * 16 + p] = c * vp - s * vq;
            V[el * 16 + q] = s * vp + c * vq;
            __syncthreads();
        }
    }
}

__device__ void invert16d(const double* Min, double* aug, double* Mout, double* fs, int* piv) {
    const int t = threadIdx.x;
    for (int i = t; i < 512; i += TB) {
        int r = i >> 5, cc = i & 31;
        aug[i] = (cc < 16) ? Min[r * 16 + cc] : ((cc - 16 == r) ? 1.0 : 0.0);
    }
    __syncthreads();
    for (int k = 0; k < 16; ++k) {
        if (t == 0) {
            int best = k; double bv = fabs(aug[k * 32 + k]);
            for (int i = k + 1; i < 16; ++i) {
                double v = fabs(aug[i * 32 + k]);
                if (v > bv) { bv = v; best = i; }
            }
            *piv = best;
        }
        __syncthreads();
        int pb = *piv;
        if (pb != k && t < 32) {
            double tmp = aug[k * 32 + t];
            aug[k * 32 + t] = aug[pb * 32 + t];
            aug[pb * 32 + t] = tmp;
        }
        __syncthreads();
        if (t == 0) fs[16] = 1.0 / aug[k * 32 + k];
        __syncthreads();
        if (t < 32) aug[k * 32 + t] *= fs[16];
        __syncthreads();
        if (t < 16) fs[t] = aug[t * 32 + k];
        __syncthreads();
        for (int i = t; i < 512; i += TB) {
            int r = i >> 5, cc = i & 31;
            if (r != k) aug[i] -= fs[r] * aug[k * 32 + cc];
        }
        __syncthreads();
    }
    for (int i = t; i < 256; i += TB) Mout[i] = aug[(i >> 4) * 32 + 16 + (i & 15)];
    __syncthreads();
}

__device__ void matmul16d(const double* A, const double* Bm, double* Cc, int m) {
    const int t = threadIdx.x;
    for (int i = t; i < m * 16; i += TB) {
        int r = i >> 4, cc = i & 15;
        double acc = 0.0;
        #pragma unroll
        for (int x = 0; x < 16; ++x) acc += A[r * 16 + x] * Bm[x * 16 + cc];
        Cc[i] = acc;
    }
    __syncthreads();
}

__device__ void gram16d(const double* A, double* W, int m) {
    const int t = threadIdx.x;
    for (int i = t; i < 256; i += TB) {
        int r = i >> 4, cc = i & 15;
        double acc = 0.0;
        for (int x = 0; x < m; ++x) acc += A[x * 16 + r] * A[x * 16 + cc];
        W[i] = acc;
    }
    __syncthreads();
}

__device__ void vdvtd(const double* V, const double* g, double* P) {
    const int t = threadIdx.x;
    for (int i = t; i < 256; i += TB) {
        int r = i >> 4, cc = i & 15;
        double acc = 0.0;
        #pragma unroll
        for (int x = 0; x < 16; ++x) acc += V[r * 16 + x] * g[x] * V[cc * 16 + x];
        P[i] = acc;
    }
    __syncthreads();
}

// ================= kernels =================

// K1 (warp-per-instance): x_log = log_map(X[0,c], X[b,c]) -> gXlog[bc]
__global__ void __launch_bounds__(TB) k1_logmap(const float* __restrict__ X) {
    __shared__ alignas(16) float Ub[WPB][1024];
    __shared__ alignas(16) float Zb[WPB][1024];
    __shared__ float Mm[WPB][272];
    const int w = threadIdx.x >> 5, lane = threadIdx.x & 31;
    const int bc = blockIdx.x * WPB + w;
    const int c = bc & (Csz - 1);
    float* U = Ub[w];
    float* Z = Zb[w];
    float* M = Mm[w];
    // overlay pointers (valid after U is dead)
    float* W    = Ub[w];          // 288 (stride-17 16x16)
    float* V    = Ub[w] + 288;    // 288
    float* T1f  = Ub[w] + 576;    // 256
    float* lamA = Ub[w] + 832;    // 16
    float* sdA  = Ub[w] + 848;    // 16
    const float4* Xp4 = (const float4*)(X + (size_t)bc * 1024);
    const float4* Up4 = (const float4*)(X + (size_t)c * 1024);
    float4* U4 = (float4*)U;
    float4* Z4 = (float4*)Z;
    for (int i = lane; i < 256; i += 32) { U4[i] = Up4[i]; Z4[i] = Xp4[i]; }
    __syncwarp();
    // M = U^T X  (vectorized; order over x preserved)
    {
        const int r = lane >> 1, ccb = (lane & 1) * 8;
        const int zoff = ccb >> 2;
        float acc0 = 0.f, acc1 = 0.f, acc2 = 0.f, acc3 = 0.f;
        float acc4 = 0.f, acc5 = 0.f, acc6 = 0.f, acc7 = 0.f;
        for (int x = 0; x < 64; ++x) {
            float u = U[x * 16 + r];
            float4 z0 = Z4[x * 4 + zoff];
            float4 z1 = Z4[x * 4 + zoff + 1];
            acc0 = __fmaf_rn(u, z0.x, acc0);
            acc1 = __fmaf_rn(u, z0.y, acc1);
            acc2 = __fmaf_rn(u, z0.z, acc2);
            acc3 = __fmaf_rn(u, z0.w, acc3);
            acc4 = __fmaf_rn(u, z1.x, acc4);
            acc5 = __fmaf_rn(u, z1.y, acc5);
            acc6 = __fmaf_rn(u, z1.z, acc6);
            acc7 = __fmaf_rn(u, z1.w, acc7);
        }
        float* Mr = M + r * S17 + ccb;
        Mr[0] = acc0; Mr[1] = acc1; Mr[2] = acc2; Mr[3] = acc3;
        Mr[4] = acc4; Mr[5] = acc5; Mr[6] = acc6; Mr[7] = acc7;
    }
    __syncwarp();
    // Z = Z - U M  (row-per-lane, 2 passes; bit-identical values)
    #pragma unroll
    for (int pass = 0; pass < 2; ++pass) {
        int r = lane + (pass << 5);
        float a[16];
        #pragma unroll
        for (int cc2 = 0; cc2 < 16; ++cc2) a[cc2] = Z[r * 16 + cc2];
        #pragma unroll
        for (int x = 0; x < 16; ++x) {
            float u = U[r * 16 + x];
            #pragma unroll
            for (int cc2 = 0; cc2 < 16; ++cc2)
                a[cc2] = __fmaf_rn(-u, M[x * S17 + cc2], a[cc2]);
        }
        #pragma unroll
        for (int cc2 = 0; cc2 < 16; ++cc2) Z[r * 16 + cc2] = a[cc2];
    }
    __syncwarp();
    // W = M M^T (bounded) into overlay
    for (int i = lane; i < 256; i += 32) {
        int r = i >> 4, cc = i & 15;
        float acc = 0.f;
        #pragma unroll
        for (int x = 0; x < 16; ++x) acc += M[r * S17 + x] * M[cc * S17 + x];
        W[r * S17 + cc] = acc;
    }
    for (int i = lane; i < 288; i += 32) V[i] = 0.f;
    __syncwarp();
    if (lane < 16) V[lane * S17 + lane] = 1.f;
    jacobi_warp(W, V, lane, SWEEPS_W, true);
    // T1 = M^T V (Kahan+TwoProd fp32)
    for (int i = lane; i < 256; i += 32) {
        int r = i >> 4, cc = i & 15;
        float s = 0.f, comp = 0.f;
        #pragma unroll
        for (int x = 0; x < 16; ++x) {
            float a = M[x * S17 + r], b = V[x * S17 + cc];
            float p = __fmul_rn(a, b);
            float e = __fmaf_rn(a, b, -p);
            float y = p - comp;
            float t2 = s + y;
            comp = ((t2 - s) - y) - e;
            s = t2;
        }
        T1f[i] = s - comp;
    }
    __syncwarp();
    if (lane < 16) {
        float acc = 0.f;
        #pragma unroll
        for (int r = 0; r < 16; ++r) { float v = T1f[r * 16 + lane]; acc = __fmaf_rn(v, v, acc); }
        lamA[lane] = fmaxf(acc, 1e-30f);
    }
    __syncwarp();
    if (lane < 16) {
        double lam = (double)lamA[lane];
        double om = fmax(1.0 - lam, 0.0);
        double alpha = (om < 1e-28) ? 1.0 : atan(sqrt(om / lam)) / sqrt(om);
        sdA[lane] = (float)(alpha / sqrt(lam));
    }
    __syncwarp();
    // Ts into M (bounded)
    for (int i = lane; i < 256; i += 32)
        M[(i >> 4) * S17 + (i & 15)] = T1f[i] * sdA[i & 15];
    __syncwarp();
    // G = Ts V^T into W slot (W dead)
    for (int i = lane; i < 256; i += 32) {
        int r = i >> 4, cc = i & 15;
        float acc = 0.f;
        #pragma unroll
        for (int x = 0; x < 16; ++x) acc += M[r * S17 + x] * V[cc * S17 + x];
        W[r * S17 + cc] = acc;
    }
    __syncwarp();
    // x_log = Z G -> gXlog  (row-per-lane, 2 passes; bit-identical values)
    float4* dst4 = (float4*)(gXlog + (size_t)bc * 1024);
    #pragma unroll
    for (int pass = 0; pass < 2; ++pass) {
        int r = lane + (pass << 5);
        float a[16];
        #pragma unroll
        for (int cc2 = 0; cc2 < 16; ++cc2) a[cc2] = 0.f;
        #pragma unroll
        for (int x = 0; x < 16; ++x) {
            float z = Z[r * 16 + x];
            #pragma unroll
            for (int cc2 = 0; cc2 < 16; ++cc2)
                a[cc2] = __fmaf_rn(z, W[x * S17 + cc2], a[cc2]);
        }
        dst4[r * 4 + 0] = make_float4(a[0], a[1], a[2], a[3]);
        dst4[r * 4 + 1] = make_float4(a[4], a[5], a[6], a[7]);
        dst4[r * 4 + 2] = make_float4(a[8], a[9], a[10], a[11]);
        dst4[r * 4 + 3] = make_float4(a[12], a[13], a[14], a[15]);
    }
}

// K2 (grid=Csz+1): blocks 0..127 per-channel mean/Bm/GinvC; block 128 bias GinvB.
__global__ void k2_mean(const float* __restrict__ X, float* __restrict__ meanOut,
                        const float* __restrict__ bias) {
    __shared__ double Dm[1024], U0[1024], meanS[1024], Cm[768];
    __shared__ double W[256], V[256], M1[256], M2[256], aug[512];
    __shared__ double g[32], cs[16], fs[18];
    __shared__ int piv;
    const int c = blockIdx.x;
    const int t = threadIdx.x;
    if (c == Csz) {
        for (int i = t; i < 768; i += TB) Cm[i] = (double)bias[i];
        __syncthreads();
        gram16d(Cm, W, 48);
        for (int i = t; i < 256; i += TB) {
            int r = i >> 4, cc = i & 15;
            W[i] = 0.25 * W[i] + ((r == cc) ? 1.0 : 0.0);
        }
        __syncthreads();
        invert16d(W, aug, M1, fs, &piv);
        for (int i = t; i < 256; i += TB) gGinvBF[i] = (float)M1[i];
        return;
    }
    const float4* gX4 = (const float4*)gXlog;
    for (int i4 = t; i4 < 256; i4 += TB) {
        float a0 = 0.f, a1 = 0.f, a2 = 0.f, a3 = 0.f;
        #pragma unroll 4
        for (int b = 0; b < Bsz; ++b) {
            float4 v = gX4[((size_t)b * Csz + c) * 256 + i4];
            a0 += v.x; a1 += v.y; a2 += v.z; a3 += v.w;
        }
        const double inv = 1.0 / (double)Bsz;
        int i = i4 * 4;
        Dm[i] = (double)a0 * inv; Dm[i + 1] = (double)a1 * inv;
        Dm[i + 2] = (double)a2 * inv; Dm[i + 3] = (double)a3 * inv;
    }
    for (int i = t; i < 1024; i += TB)
        U0[i] = (double)X[(size_t)c * 1024 + i];
    __syncthreads();
    gram16d(Dm, W, 64);
    jacobi16d(W, V, cs);
    if (t < 16) {
        double S = sqrt(fmax(W[t * 17], 0.0));
        g[t] = cos(S);
        g[16 + t] = (S > 1e-100) ? sin(S) / S : 1.0;
    }
    __syncthreads();
    vdvtd(V, g, M1);
    vdvtd(V, g + 16, M2);
    for (int i = t; i < 1024; i += TB) {
        int r = i >> 4, cc = i & 15;
        double acc = 0.0;
        #pragma unroll
        for (int x = 0; x < 16; ++x)
            acc += U0[r * 16 + x] * M1[x * 16 + cc] + Dm[r * 16 + x] * M2[x * 16 + cc];
        meanS[i] = acc;
        meanOut[c * 1024 + i] = (float)acc;
    }
    __syncthreads();
    invert16d(meanS, aug, M1, fs, &piv);
    matmul16d(meanS + 256, M1, Cm, 48);
    gram16d(Cm, W, 48);
    jacobi16d(W, V, cs);
    if (t < 16) {
        double S = sqrt(fmax(W[t * 17], 0.0));
        g[t] = (S > 1e-100) ? atan(S) / S : 1.0;
    }
    __syncthreads();
    vdvtd(V, g, M2);
    matmul16d(Cm, M2, Dm, 48);
    for (int i = t; i < 768; i += TB) gBmF[c * 768 + i] = (float)Dm[i];
    __syncthreads();
    gram16d(Dm, W, 48);
    for (int i = t; i < 256; i += TB) {
        int r = i >> 4, cc = i & 15;
        W[i] = 0.25 * W[i] + ((r == cc) ? 1.0 : 0.0);
    }
    __syncthreads();
    invert16d(W, aug, M1, fs, &piv);
    for (int i = t; i < 256; i += TB) gGinvCF[c * 256 + i] = (float)M1[i];
}

// K3 (warp-per-instance): theta^2 sum -> gTheta[bc]
__global__ void __launch_bounds__(TB) k3_theta(const float* __restrict__ X,
                                               const float* __restrict__ meanIn) {
    __shared__ alignas(16) float Mn[WPB][1024];
    __shared__ alignas(16) float Xb[WPB][1024];
    __shared__ float Mm[WPB][272];
    const int w = threadIdx.x >> 5, lane = threadIdx.x & 31;
    const int bc = blockIdx.x * WPB + w;
    const int c = bc & (Csz - 1);
    float* A = Mn[w];
    float* Xl = Xb[w];
    float* M = Mm[w];
    float* W = Mn[w];              // overlay (mean dead after M computed)
    const float4* Xp4 = (const float4*)(X + (size_t)bc * 1024);
    const float4* Mp4 = (const float4*)(meanIn + (size_t)c * 1024);
    float4* A4 = (float4*)A;
    float4* Xl4 = (float4*)Xl;
    for (int i = lane; i < 256; i += 32) { A4[i] = Mp4[i]; Xl4[i] = Xp4[i]; }
    __syncwarp();
    {
        const int r = lane >> 1, ccb = (lane & 1) * 8;
        const int zoff = ccb >> 2;
        float acc0 = 0.f, acc1 = 0.f, acc2 = 0.f, acc3 = 0.f;
        float acc4 = 0.f, acc5 = 0.f, acc6 = 0.f, acc7 = 0.f;
        for (int x = 0; x < 64; ++x) {
            float u = A[x * 16 + r];
            float4 z0 = Xl4[x * 4 + zoff];
            float4 z1 = Xl4[x * 4 + zoff + 1];
            acc0 = __fmaf_rn(u, z0.x, acc0);
            acc1 = __fmaf_rn(u, z0.y, acc1);
            acc2 = __fmaf_rn(u, z0.z, acc2);
            acc3 = __fmaf_rn(u, z0.w, acc3);
            acc4 = __fmaf_rn(u, z1.x, acc4);
            acc5 = __fmaf_rn(u, z1.y, acc5);
            acc6 = __fmaf_rn(u, z1.z, acc6);
            acc7 = __fmaf_rn(u, z1.w, acc7);
        }
        float* Mr = M + r * S17 + ccb;
        Mr[0] = acc0; Mr[1] = acc1; Mr[2] = acc2; Mr[3] = acc3;
        Mr[4] = acc4; Mr[5] = acc5; Mr[6] = acc6; Mr[7] = acc7;
    }
    __syncwarp();
    for (int i = lane; i < 256; i += 32) {
        int r = i >> 4, cc = i & 15;
        float acc = 0.f;
        #pragma unroll
        for (int x = 0; x < 16; ++x) acc += M[x * S17 + r] * M[x * S17 + cc];
        W[r * S17 + cc] = acc;
    }
    __syncwarp();
    jacobi_warp(W, (float*)0, lane, SWEEPS_NV, false);
    if (lane == 0) {
        float sum = 0.f;
        for (int j2 = 0; j2 < 16; ++j2) {
            float s = sqrtf(fmaxf(W[j2 * 18], 0.f));
            s = fminf(s, 1.f);
            float th = acosf(s);
            sum += th * th;
        }
        gTheta[bc] = sum;
    }
}

// K4 (grid=Csz): per-channel factor via tree reduction only
__global__ void k4_factor(const float* __restrict__ shiftp) {
    __shared__ float red[TB];
    const int t = threadIdx.x;
    const int c = blockIdx.x;
    red[t] = gTheta[t * Csz + c] + gTheta[(t + TB) * Csz + c];
    __syncthreads();
    for (int s = TB / 2; s > 0; s >>= 1) {
        if (t < s) red[t] += red[t + s];
        __syncthreads();
    }
    if (t == 0) {
        double var = (double)red[0] * (1.0 / (double)Bsz);
        gFactorF[c] = (float)((double)shiftp[0] / sqrt(var + 1e-5));
    }
}

// K5 (warp-per-instance): center -> gyro scale -> bias
__global__ void __launch_bounds__(TB) k5_final(const float* __restrict__ X,
                                               const float* __restrict__ bias,
                                               float* __restrict__ out) {
    __shared__ alignas(16) float Xs[WPB][1024];
    __shared__ alignas(16) float Bmw[WPB][768];   // Bm -> V -> bot -> bias
    __shared__ alignas(16) float bufa[WPB][512];  // Ginv/W -> T1f,Tsf -> M2 / GinvB
    __shared__ alignas(16) float Tt[WPB][256];    // T (A) -> top -> T (C)
    __shared__ float lamK[WPB][16], sdK[WPB][16], gkK[WPB][16];
    const int w = threadIdx.x >> 5, lane = threadIdx.x & 31;
    const int bc = blockIdx.x * WPB + w;
    const int c = bc & (Csz - 1);
    float* Xw = Xs[w];
    float* Bw = Bmw[w];
    float* buf_f = bufa[w];
    float* T = Tt[w];
    {
        const float4* Xp4 = (const float4*)(X + (size_t)bc * 1024);
        const float4* Bm4 = (const float4*)(gBmF + (size_t)c * 768);
        const float4* Gi4 = (const float4*)(gGinvCF + (size_t)c * 256);
        float4* Xw4 = (float4*)Xw;
        float4* Bw4 = (float4*)Bw;
        float4* bf4 = (float4*)buf_f;
        for (int i = lane; i < 256; i += 32) Xw4[i] = Xp4[i];
        for (int i = lane; i < 192; i += 32) Bw4[i] = Bm4[i];
        for (int i = lane; i < 64; i += 32) bf4[i] = Gi4[i];
    }
    __syncwarp();
    // --- Step A: centering Cayley (vectorized 48-loop; order preserved) ---
    {
        const int r = lane >> 1, ccb = (lane & 1) * 8;
        const int zoff = ccb >> 2;
        const float4* Xl4 = (const float4*)(Xw + 256);
        float a0 = Xw[r * 16 + ccb],     a1 = Xw[r * 16 + ccb + 1];
        float a2 = Xw[r * 16 + ccb + 2], a3 = Xw[r * 16 + ccb + 3];
        float a4 = Xw[r * 16 + ccb + 4], a5 = Xw[r * 16 + ccb + 5];
        float a6 = Xw[r * 16 + ccb + 6], a7 = Xw[r * 16 + ccb + 7];
        for (int k = 0; k < 48; ++k) {
            float b = 0.5f * Bw[k * 16 + r];
            float4 z0 = Xl4[k * 4 + zoff];
            float4 z1 = Xl4[k * 4 + zoff + 1];
            a0 = __fmaf_rn(b, z0.x, a0);
            a1 = __fmaf_rn(b, z0.y, a1);
            a2 = __fmaf_rn(b, z0.z, a2);
            a3 = __fmaf_rn(b, z0.w, a3);
            a4 = __fmaf_rn(b, z1.x, a4);
            a5 = __fmaf_rn(b, z1.y, a5);
            a6 = __fmaf_rn(b, z1.z, a6);
            a7 = __fmaf_rn(b, z1.w, a7);
        }
        float4* T4w = (float4*)T;
        T4w[(r * 16 + ccb) >> 2]       = make_float4(a0, a1, a2, a3);
        T4w[((r * 16 + ccb) >> 2) + 1] = make_float4(a4, a5, a6, a7);
    }
    __syncwarp();
    {
        float yreg[8];
        #pragma unroll
        for (int ii = 0; ii < 8; ++ii) {
            int i = lane + 32 * ii, r = i >> 4, cc = i & 15;
            float acc = 0.f;
            #pragma unroll
            for (int x = 0; x < 16; ++x) acc += buf_f[r * 16 + x] * T[x * 16 + cc];
            yreg[ii] = acc;
        }
        __syncwarp();
        #pragma unroll
        for (int ii = 0; ii < 8; ++ii) T[lane + 32 * ii] = yreg[ii];
    }
    __syncwarp();
    // Xu = 2Y - Xu
    for (int i = lane; i < 256; i += 32) Xw[i] = 2.f * T[i] - Xw[i];
    // Xl = Xl - Bm Y  (row-per-lane; bit-identical values)
    #pragma unroll
    for (int pass = 0; pass < 2; ++pass) {
        int r = lane + (pass << 5);
        if (r < 48) {
            float a[16];
            #pragma unroll
            for (int cc2 = 0; cc2 < 16; ++cc2) a[cc2] = Xw[256 + r * 16 + cc2];
            #pragma unroll
            for (int x = 0; x < 16; ++x) {
                float b = Bw[r * 16 + x];
                #pragma unroll
                for (int cc2 = 0; cc2 < 16; ++cc2)
                    a[cc2] = __fmaf_rn(-b, T[x * 16 + cc2], a[cc2]);
            }
            #pragma unroll
            for (int cc2 = 0; cc2 < 16; ++cc2) Xw[256 + r * 16 + cc2] = a[cc2];
        }
    }
    __syncwarp();
    // --- Step B: gyro scaling via K = Xu Xu^T ---
    float* W = buf_f;                          // Ginv dead
    float* V = Bw;                             // Bm dead; V stride-17 in Bmw[0..287]
    for (int i = lane; i < 256; i += 32) {
        int r = i >> 4, cc = i & 15;
        float acc = 0.f;
        #pragma unroll
        for (int x = 0; x < 16; ++x) acc += Xw[r * 16 + x] * Xw[cc * 16 + x];
        W[r * S17 + cc] = acc;
    }
    for (int i = lane; i < 288; i += 32) V[i] = 0.f;
    __syncwarp();
    if (lane < 16) V[lane * S17 + lane] = 1.f;
    jacobi_warp(W, V, lane, SWEEPS_W, true);
    // ---- compensated fp32 T1 (W dead) ----
    float* T1f = buf_f;          // 256
    for (int i = lane; i < 256; i += 32) {
        int r = i >> 4, cc = i & 15;
        float s = 0.f, comp = 0.f;
        #pragma unroll
        for (int x = 0; x < 16; ++x) {
            float a = Xw[x * 16 + r], b = V[x * S17 + cc];
            float p = __fmul_rn(a, b);
            float e = __fmaf_rn(a, b, -p);
            float y = p - comp;
            float t2 = s + y;
            comp = ((t2 - s) - y) - e;
            s = t2;
        }
        T1f[i] = s - comp;
    }
    __syncwarp();
    if (lane < 16) {
        float acc = 0.f;
        #pragma unroll
        for (int r = 0; r < 16; ++r) { float v = T1f[r * 16 + lane]; acc = __fmaf_rn(v, v, acc); }
        lamK[w][lane] = fmaxf(acc, 1e-30f);
    }
    __syncwarp();
    float fct = gFactorF[c];
    if (lane < 16) {
        double lam = (double)lamK[w][lane];
        double om = fmax(1.0 - lam, 0.0);
        double beta, cth;
        if (om < 1e-28) { beta = (double)fct; cth = 1.0; }
        else {
            double th = (double)fct * atan(sqrt(om / lam));
            beta = sin(th) / sqrt(om);
            cth = cos(th);
        }
        sdK[w][lane] = (float)(beta / sqrt(lam));
        gkK[w][lane] = (float)cth;
    }
    __syncwarp();
    float* Tsf = buf_f + 256;
    for (int i = lane; i < 256; i += 32) Tsf[i] = T1f[i] * sdK[w][i & 15];
    __syncwarp();
    // M2 = Ts V^T and top = V cos V^T, staged; commit M2 -> buf_f[0..255], top -> T
    {
        float m2reg[8], topreg[8];
        #pragma unroll
        for (int ii = 0; ii < 8; ++ii) {
            int i = lane + 32 * ii, r = i >> 4, cc = i & 15;
            float accm = 0.f, acct = 0.f;
            #pragma unroll
            for (int x = 0; x < 16; ++x) {
                accm += Tsf[r * 16 + x] * V[cc * S17 + x];
                acct += V[r * S17 + x] * gkK[w][x] * V[cc * S17 + x];
            }
            m2reg[ii] = accm;
            topreg[ii] = acct;
        }
        __syncwarp();
        #pragma unroll
        for (int ii = 0; ii < 8; ++ii) {
            buf_f[lane + 32 * ii] = m2reg[ii];   // M2
            T[lane + 32 * ii] = topreg[ii];      // top
        }
    }
    __syncwarp();
    // bot = Xl M2 into Bw (V dead) — vectorized: 3 chunks of 16 rows
    {
        const int rh = lane >> 1, ccb = (lane & 1) * 8;
        const int moff = ccb >> 2;
        const float4* M24 = (const float4*)buf_f;
        #pragma unroll
        for (int chunk = 0; chunk < 3; ++chunk) {
            int row = rh + (chunk << 4);
            float a0 = 0.f, a1 = 0.f, a2 = 0.f, a3 = 0.f;
            float a4 = 0.f, a5 = 0.f, a6 = 0.f, a7 = 0.f;
            #pragma unroll
            for (int x = 0; x < 16; ++x) {
                float a = Xw[256 + row * 16 + x];
                float4 m0 = M24[x * 4 + moff];
                float4 m1 = M24[x * 4 + moff + 1];
                a0 = __fmaf_rn(a, m0.x, a0);
                a1 = __fmaf_rn(a, m0.y, a1);
                a2 = __fmaf_rn(a, m0.z, a2);
                a3 = __fmaf_rn(a, m0.w, a3);
                a4 = __fmaf_rn(a, m1.x, a4);
                a5 = __fmaf_rn(a, m1.y, a5);
                a6 = __fmaf_rn(a, m1.z, a6);
                a7 = __fmaf_rn(a, m1.w, a7);
            }
            float4* Bw4w = (float4*)Bw;
            Bw4w[(row * 16 + ccb) >> 2]       = make_float4(a0, a1, a2, a3);
            Bw4w[((row * 16 + ccb) >> 2) + 1] = make_float4(a4, a5, a6, a7);
        }
    }
    __syncwarp();
    // commit: Xu=top, Xl=bot
    {
        float4* Xw4 = (float4*)Xw;
        float4* T4 = (float4*)T;
        float4* Bw4 = (float4*)Bw;
        for (int i = lane; i < 64; i += 32) Xw4[i] = T4[i];
        for (int i = lane; i < 192; i += 32) Xw4[64 + i] = Bw4[i];
    }
    __syncwarp();
    // --- Step C: bias Cayley ---
    {
        const float4* b4 = (const float4*)bias;
        const float4* g4 = (const float4*)gGinvBF;
        float4* Bw4 = (float4*)Bw;
        float4* bf4 = (float4*)buf_f;
        for (int i = lane; i < 192; i += 32) Bw4[i] = b4[i];
        for (int i = lane; i < 64; i += 32) bf4[i] = g4[i];
    }
    __syncwarp();
    {
        const int r = lane >> 1, ccb = (lane & 1) * 8;
        const int zoff = ccb >> 2;
        const float4* Xl4 = (const float4*)(Xw + 256);
        float a0 = Xw[r * 16 + ccb],     a1 = Xw[r * 16 + ccb + 1];
        float a2 = Xw[r * 16 + ccb + 2], a3 = Xw[r * 16 + ccb + 3];
        float a4 = Xw[r * 16 + ccb + 4], a5 = Xw[r * 16 + ccb + 5];
        float a6 = Xw[r * 16 + ccb + 6], a7 = Xw[r * 16 + ccb + 7];
        for (int k = 0; k < 48; ++k) {
            float b = 0.5f * Bw[k * 16 + r];
            float4 z0 = Xl4[k * 4 + zoff];
            float4 z1 = Xl4[k * 4 + zoff + 1];
            a0 = __fmaf_rn(-b, z0.x, a0);
            a1 = __fmaf_rn(-b, z0.y, a1);
            a2 = __fmaf_rn(-b, z0.z, a2);
            a3 = __fmaf_rn(-b, z0.w, a3);
            a4 = __fmaf_rn(-b, z1.x, a4);
            a5 = __fmaf_rn(-b, z1.y, a5);
            a6 = __fmaf_rn(-b, z1.z, a6);
            a7 = __fmaf_rn(-b, z1.w, a7);
        }
        float4* T4w = (float4*)T;
        T4w[(r * 16 + ccb) >> 2]       = make_float4(a0, a1, a2, a3);
        T4w[((r * 16 + ccb) >> 2) + 1] = make_float4(a4, a5, a6, a7);
    }
    __syncwarp();
    {
        float yreg[8];
        #pragma unroll
        for (int ii = 0; ii < 8; ++ii) {
            int i = lane + 32 * ii, r = i >> 4, cc = i & 15;
            float acc = 0.f;
            #pragma unroll
            for (int x = 0; x < 16; ++x) acc += buf_f[r * 16 + x] * T[x * 16 + cc];
            yreg[ii] = acc;
        }
        __syncwarp();
        #pragma unroll
        for (int ii = 0; ii < 8; ++ii) T[lane + 32 * ii] = yreg[ii];
    }
    __syncwarp();
    float4* dst4 = (float4*)(out + (size_t)bc * 1024);
    for (int i4 = lane; i4 < 64; i4 += 32) {
        float4 t4 = ((float4*)T)[i4];
        float4 x4 = ((float4*)Xw)[i4];
        dst4[i4] = make_float4(2.f * t4.x - x4.x, 2.f * t4.y - x4.y,
                               2.f * t4.z - x4.z, 2.f * t4.w - x4.w);
    }
    // out lower 48 rows: Xl + bias*Y  (row-per-lane; bit-identical values)
    #pragma unroll
    for (int pass = 0; pass < 2; ++pass) {
        int r = lane + (pass << 5);
        if (r < 48) {
            float a[16];
            #pragma unroll
            for (int cc2 = 0; cc2 < 16; ++cc2) a[cc2] = Xw[256 + r * 16 + cc2];
            #pragma unroll
            for (int x = 0; x < 16; ++x) {
                float b = Bw[r * 16 + x];
                #pragma unroll
                for (int cc2 = 0; cc2 < 16; ++cc2)
                    a[cc2] = __fmaf_rn(b, T[x * 16 + cc2], a[cc2]);
            }
            dst4[64 + r * 4 + 0] = make_float4(a[0], a[1], a[2], a[3]);
            dst4[64 + r * 4 + 1] = make_float4(a[4], a[5], a[6], a[7]);
            dst4[64 + r * 4 + 2] = make_float4(a[8], a[9], a[10], a[11]);
            dst4[64 + r * 4 + 3] = make_float4(a[12], a[13], a[14], a[15]);
        }
    }
}

// ---------------- launch ----------------
extern "C" void kernel_launch(void* const* d_in, const int* in_sizes, int n_in,
                              void* d_out, int out_size) {
    const float* X = (const float*)d_in[0];
    const float* bias = (const float*)d_in[1];
    const float* shift = (const float*)d_in[2];
    float* out = (float*)d_out;
    float* meanOut = out + (size_t)Bsz * Csz * Nsz * Psz;

    const int nInst = Bsz * Csz;
    k1_logmap<<<nInst / WPB, TB>>>(X);
    k2_mean<<<Csz + 1, TB>>>(X, meanOut, bias);
    k3_theta<<<nInst / WPB, TB>>>(X, meanOut);
    k4_factor<<<Csz, TB>>>(shift);
    k5_final<<<nInst / WPB, TB>>>(X, bias, out);
}

// round 17
// speedup vs baseline: 1.3014x; 1.3014x over previous
#include <cuda_runtime.h>

#define Bsz 256
#define Csz 128
#define Nsz 64
#define Psz 16
#define Qsz 48
#define TB 128
#define WPB 4
#define SWEEPS_W 6
#define SWEEPS_NV 4
#define SWEEPS_D 5
#define S17 17
#define JTOL 1e-13f
#define FULLM 0xffffffffu

// ---------------- device scratch (static, no allocations) ----------------
__device__ alignas(16) float gXlog[(size_t)Bsz * Csz * Nsz * Psz]; // 128MB
__device__ float gTheta[Bsz * Csz];
__device__ alignas(16) float gBmF[Csz * Qsz * Psz];
__device__ alignas(16) float gGinvCF[Csz * Psz * Psz];
__device__ alignas(16) float gGinvBF[Psz * Psz];
__device__ float gFactorF[Csz];

// tournament pair k at round r (p > q)
__device__ __forceinline__ void pqk(int k, int r, int& p, int& q) {
    if (k == 0) { p = 15; q = r; }
    else {
        p = r + k; if (p >= 15) p -= 15;
        q = r + 15 - k; if (q >= 15) q -= 15;
    }
    if (p < q) { int t = p; p = q; q = t; }
}

// ================= warp-level fp32 Jacobi: fused 2x2-block rounds =================
// Each lane owns blocks (i0, jb) and (i0+4, jb); applies row+col rotation locally.
// Bit-identical to the two-phase (row then col) update.
__device__ __forceinline__ void jacobi_warp(float* W, float* V, int lane,
                                            int sweeps, bool wantV) {
    const int jv = lane >> 2;         // V col-pair
    const int b4v = (lane & 3) * 4;   // V row base
    const int i0 = lane >> 3;         // W block row-pair (block 0)
    const int jb = lane & 7;          // W block col-pair
    for (int sweep = 0; sweep < sweeps; ++sweep) {
        if (sweep >= sweeps - 2) {
            __syncwarp();
            float acc = 0.f;
            #pragma unroll
            for (int ii = 0; ii < 8; ++ii) {
                int i = lane + 32 * ii;
                int r = i >> 4, cc = i & 15;
                float v = (r < cc) ? W[r * S17 + cc] : 0.f;
                acc = __fmaf_rn(v, v, acc);
            }
            #pragma unroll
            for (int off = 16; off; off >>= 1)
                acc += __shfl_xor_sync(FULLM, acc, off);
            if (acc < JTOL) break;
        }
        for (int r = 0; r < 15; ++r) {
            __syncwarp();
            float cv = 1.f, sv = 0.f;
            if (lane < 8) {
                int p, q; pqk(lane, r, p, q);
                float app = W[p * S17 + p], aqq = W[q * S17 + q], apq = W[p * S17 + q];
                if (fabsf(apq) > 1e-37f) {
                    float tau = (aqq - app) / (2.f * apq);
                    float tt = copysignf(1.f, tau) / (fabsf(tau) + sqrtf(1.f + tau * tau));
                    cv = rsqrtf(1.f + tt * tt);
                    sv = tt * cv;
                }
            }
            float ci0 = __shfl_sync(FULLM, cv, i0),     si0 = __shfl_sync(FULLM, sv, i0);
            float ci1 = __shfl_sync(FULLM, cv, i0 + 4), si1 = __shfl_sync(FULLM, sv, i0 + 4);
            float cjb = __shfl_sync(FULLM, cv, jb),     sjb = __shfl_sync(FULLM, sv, jb);
            int pj, qj; pqk(jb, r, pj, qj);
            {   // block 0: rows pair i0
                int pi, qi; pqk(i0, r, pi, qi);
                float wpp = W[pi * S17 + pj], wpq = W[pi * S17 + qj];
                float wqp = W[qi * S17 + pj], wqq = W[qi * S17 + qj];
                float rpp = ci0 * wpp - si0 * wqp;
                float rpq = ci0 * wpq - si0 * wqq;
                float rqp = si0 * wpp + ci0 * wqp;
                float rqq = si0 * wpq + ci0 * wqq;
                W[pi * S17 + pj] = cjb * rpp - sjb * rpq;
                W[pi * S17 + qj] = sjb * rpp + cjb * rpq;
                W[qi * S17 + pj] = cjb * rqp - sjb * rqq;
                W[qi * S17 + qj] = sjb * rqp + cjb * rqq;
            }
            {   // block 1: rows pair i0+4
                int pi, qi; pqk(i0 + 4, r, pi, qi);
                float wpp = W[pi * S17 + pj], wpq = W[pi * S17 + qj];
                float wqp = W[qi * S17 + pj], wqq = W[qi * S17 + qj];
                float rpp = ci1 * wpp - si1 * wqp;
                float rpq = ci1 * wpq - si1 * wqq;
                float rqp = si1 * wpp + ci1 * wqp;
                float rqq = si1 * wpq + ci1 * wqq;
                W[pi * S17 + pj] = cjb * rpp - sjb * rpq;
                W[pi * S17 + qj] = sjb * rpp + cjb * rpq;
                W[qi * S17 + pj] = cjb * rqp - sjb * rqq;
                W[qi * S17 + qj] = sjb * rqp + cjb * rqq;
            }
            if (wantV) {
                float cjv = __shfl_sync(FULLM, cv, jv), sjv = __shfl_sync(FULLM, sv, jv);
                int pv, qv; pqk(jv, r, pv, qv);
                #pragma unroll
                for (int k = 0; k < 4; ++k) {
                    int row = b4v + k;
                    float vp = V[row * S17 + pv], vq = V[row * S17 + qv];
                    V[row * S17 + pv] = cjv * vp - sjv * vq;
                    V[row * S17 + qv] = sjv * vp + cjv * vq;
                }
            }
        }
    }
    __syncwarp();
}

// ================= block-level fp64 helpers (k2) =================
__device__ void jacobi16d(double* W, double* V, double* cs) {
    const int t = threadIdx.x;
    for (int i = t; i < 256; i += TB) V[i] = ((i >> 4) == (i & 15)) ? 1.0 : 0.0;
    __syncthreads();
    const int pr = t >> 4, el = t & 15;
    for (int sweep = 0; sweep < SWEEPS_D; ++sweep) {
        for (int r = 0; r < 15; ++r) {
            int p, q;
            if (pr == 0) { p = 15; q = r; }
            else { p = (r + pr) % 15; q = (r + 15 - pr) % 15; }
            if (p < q) { int tmp = p; p = q; q = tmp; }
            if (el == 0) {
                double app = W[p * 16 + p], aqq = W[q * 16 + q], apq = W[p * 16 + q];
                double c = 1.0, s = 0.0;
                if (fabs(apq) > 1e-300) {
                    double tau = (aqq - app) / (2.0 * apq);
                    double tt = copysign(1.0, tau) / (fabs(tau) + sqrt(1.0 + tau * tau));
                    c = rsqrt(1.0 + tt * tt);
                    s = tt * c;
                }
                cs[pr] = c; cs[8 + pr] = s;
            }
            __syncthreads();
            double c = cs[pr], s = cs[8 + pr];
            double wp = W[p * 16 + el], wq = W[q * 16 + el];
            W[p * 16 + el] = c * wp - s * wq;
            W[q * 16 + el] = s * wp + c * wq;
            __syncthreads();
            double xp = W[el * 16 + p], xq = W[el * 16 + q];
            W[el * 16 + p] = c * xp - s * xq;
            W[el * 16 + q] = s * xp + c * xq;
            double vp = V[el * 16 + p], vq = V[el * 16 + q];
            V[el * 16 + p] = c * vp - s * vq;
            V[el * 16 + q] = s * vp + c * vq;
            __syncthreads();
        }
    }
}

__device__ void invert16d(const double* Min, double* aug, double* Mout, double* fs, int* piv) {
    const int t = threadIdx.x;
    for (int i = t; i < 512; i += TB) {
        int r = i >> 5, cc = i & 31;
        aug[i] = (cc < 16) ? Min[r * 16 + cc] : ((cc - 16 == r) ? 1.0 : 0.0);
    }
    __syncthreads();
    for (int k = 0; k < 16; ++k) {
        if (t == 0) {
            int best = k; double bv = fabs(aug[k * 32 + k]);
            for (int i = k + 1; i < 16; ++i) {
                double v = fabs(aug[i * 32 + k]);
                if (v > bv) { bv = v; best = i; }
            }
            *piv = best;
        }
        __syncthreads();
        int pb = *piv;
        if (pb != k && t < 32) {
            double tmp = aug[k * 32 + t];
            aug[k * 32 + t] = aug[pb * 32 + t];
            aug[pb * 32 + t] = tmp;
        }
        __syncthreads();
        if (t == 0) fs[16] = 1.0 / aug[k * 32 + k];
        __syncthreads();
        if (t < 32) aug[k * 32 + t] *= fs[16];
        __syncthreads();
        if (t < 16) fs[t] = aug[t * 32 + k];
        __syncthreads();
        for (int i = t; i < 512; i += TB) {
            int r = i >> 5, cc = i & 31;
            if (r != k) aug[i] -= fs[r] * aug[k * 32 + cc];
        }
        __syncthreads();
    }
    for (int i = t; i < 256; i += TB) Mout[i] = aug[(i >> 4) * 32 + 16 + (i & 15)];
    __syncthreads();
}

__device__ void matmul16d(const double* A, const double* Bm, double* Cc, int m) {
    const int t = threadIdx.x;
    for (int i = t; i < m * 16; i += TB) {
        int r = i >> 4, cc = i & 15;
        double acc = 0.0;
        #pragma unroll
        for (int x = 0; x < 16; ++x) acc += A[r * 16 + x] * Bm[x * 16 + cc];
        Cc[i] = acc;
    }
    __syncthreads();
}

__device__ void gram16d(const double* A, double* W, int m) {
    const int t = threadIdx.x;
    for (int i = t; i < 256; i += TB) {
        int r = i >> 4, cc = i & 15;
        double acc = 0.0;
        for (int x = 0; x < m; ++x) acc += A[x * 16 + r] * A[x * 16 + cc];
        W[i] = acc;
    }
    __syncthreads();
}

__device__ void vdvtd(const double* V, const double* g, double* P) {
    const int t = threadIdx.x;
    for (int i = t; i < 256; i += TB) {
        int r = i >> 4, cc = i & 15;
        double acc = 0.0;
        #pragma unroll
        for (int x = 0; x < 16; ++x) acc += V[r * 16 + x] * g[x] * V[cc * 16 + x];
        P[i] = acc;
    }
    __syncthreads();
}

// ================= kernels =================

// K1 (warp-per-instance): x_log = log_map(X[0,c], X[b,c]) -> gXlog[bc]
__global__ void __launch_bounds__(TB) k1_logmap(const float* __restrict__ X) {
    __shared__ alignas(16) float Ub[WPB][1024];
    __shared__ alignas(16) float Zb[WPB][1024];
    __shared__ float Mm[WPB][272];
    const int w = threadIdx.x >> 5, lane = threadIdx.x & 31;
    const int bc = blockIdx.x * WPB + w;
    const int c = bc & (Csz - 1);
    float* U = Ub[w];
    float* Z = Zb[w];
    float* M = Mm[w];
    // overlay pointers (valid after U is dead)
    float* W    = Ub[w];          // 288 (stride-17 16x16)
    float* V    = Ub[w] + 288;    // 288
    float* T1f  = Ub[w] + 576;    // 256
    float* lamA = Ub[w] + 832;    // 16
    float* sdA  = Ub[w] + 848;    // 16
    const float4* Xp4 = (const float4*)(X + (size_t)bc * 1024);
    const float4* Up4 = (const float4*)(X + (size_t)c * 1024);
    float4* U4 = (float4*)U;
    float4* Z4 = (float4*)Z;
    for (int i = lane; i < 256; i += 32) { U4[i] = Up4[i]; Z4[i] = Xp4[i]; }
    __syncwarp();
    // M = U^T X  (vectorized; order over x preserved)
    {
        const int r = lane >> 1, ccb = (lane & 1) * 8;
        const int zoff = ccb >> 2;
        float acc0 = 0.f, acc1 = 0.f, acc2 = 0.f, acc3 = 0.f;
        float acc4 = 0.f, acc5 = 0.f, acc6 = 0.f, acc7 = 0.f;
        for (int x = 0; x < 64; ++x) {
            float u = U[x * 16 + r];
            float4 z0 = Z4[x * 4 + zoff];
            float4 z1 = Z4[x * 4 + zoff + 1];
            acc0 = __fmaf_rn(u, z0.x, acc0);
            acc1 = __fmaf_rn(u, z0.y, acc1);
            acc2 = __fmaf_rn(u, z0.z, acc2);
            acc3 = __fmaf_rn(u, z0.w, acc3);
            acc4 = __fmaf_rn(u, z1.x, acc4);
            acc5 = __fmaf_rn(u, z1.y, acc5);
            acc6 = __fmaf_rn(u, z1.z, acc6);
            acc7 = __fmaf_rn(u, z1.w, acc7);
        }
        float* Mr = M + r * S17 + ccb;
        Mr[0] = acc0; Mr[1] = acc1; Mr[2] = acc2; Mr[3] = acc3;
        Mr[4] = acc4; Mr[5] = acc5; Mr[6] = acc6; Mr[7] = acc7;
    }
    __syncwarp();
    // Z = Z - U M
    for (int i = lane; i < 1024; i += 32) {
        int r = i >> 4, cc = i & 15;
        float acc = Z[i];
        #pragma unroll
        for (int x = 0; x < 16; ++x) acc -= U[r * 16 + x] * M[x * S17 + cc];
        Z[i] = acc;
    }
    __syncwarp();
    // W = M M^T (bounded) into overlay
    for (int i = lane; i < 256; i += 32) {
        int r = i >> 4, cc = i & 15;
        float acc = 0.f;
        #pragma unroll
        for (int x = 0; x < 16; ++x) acc += M[r * S17 + x] * M[cc * S17 + x];
        W[r * S17 + cc] = acc;
    }
    for (int i = lane; i < 288; i += 32) V[i] = 0.f;
    __syncwarp();
    if (lane < 16) V[lane * S17 + lane] = 1.f;
    jacobi_warp(W, V, lane, SWEEPS_W, true);
    // T1 = M^T V (Kahan+TwoProd fp32)
    for (int i = lane; i < 256; i += 32) {
        int r = i >> 4, cc = i & 15;
        float s = 0.f, comp = 0.f;
        #pragma unroll
        for (int x = 0; x < 16; ++x) {
            float a = M[x * S17 + r], b = V[x * S17 + cc];
            float p = __fmul_rn(a, b);
            float e = __fmaf_rn(a, b, -p);
            float y = p - comp;
            float t2 = s + y;
            comp = ((t2 - s) - y) - e;
            s = t2;
        }
        T1f[i] = s - comp;
    }
    __syncwarp();
    if (lane < 16) {
        float acc = 0.f;
        #pragma unroll
        for (int r = 0; r < 16; ++r) { float v = T1f[r * 16 + lane]; acc = __fmaf_rn(v, v, acc); }
        lamA[lane] = fmaxf(acc, 1e-30f);
    }
    __syncwarp();
    if (lane < 16) {
        double lam = (double)lamA[lane];
        double om = fmax(1.0 - lam, 0.0);
        double alpha = (om < 1e-28) ? 1.0 : atan(sqrt(om / lam)) / sqrt(om);
        sdA[lane] = (float)(alpha / sqrt(lam));
    }
    __syncwarp();
    // Ts into M (bounded)
    for (int i = lane; i < 256; i += 32)
        M[(i >> 4) * S17 + (i & 15)] = T1f[i] * sdA[i & 15];
    __syncwarp();
    // G = Ts V^T into W slot (W dead)
    for (int i = lane; i < 256; i += 32) {
        int r = i >> 4, cc = i & 15;
        float acc = 0.f;
        #pragma unroll
        for (int x = 0; x < 16; ++x) acc += M[r * S17 + x] * V[cc * S17 + x];
        W[r * S17 + cc] = acc;
    }
    __syncwarp();
    // x_log = Z G -> gXlog
    float4* dst4 = (float4*)(gXlog + (size_t)bc * 1024);
    for (int i4 = lane; i4 < 256; i4 += 32) {
        int r = i4 >> 2, cb = (i4 & 3) * 4;
        float a0 = 0.f, a1 = 0.f, a2 = 0.f, a3 = 0.f;
        #pragma unroll
        for (int x = 0; x < 16; ++x) {
            float z = Z[r * 16 + x];
            a0 += z * W[x * S17 + cb];
            a1 += z * W[x * S17 + cb + 1];
            a2 += z * W[x * S17 + cb + 2];
            a3 += z * W[x * S17 + cb + 3];
        }
        dst4[i4] = make_float4(a0, a1, a2, a3);
    }
}

// K2 (grid=Csz+1): blocks 0..127 per-channel mean/Bm/GinvC; block 128 bias GinvB.
__global__ void k2_mean(const float* __restrict__ X, float* __restrict__ meanOut,
                        const float* __restrict__ bias) {
    __shared__ double Dm[1024], U0[1024], meanS[1024], Cm[768];
    __shared__ double W[256], V[256], M1[256], M2[256], aug[512];
    __shared__ double g[32], cs[16], fs[18];
    __shared__ int piv;
    const int c = blockIdx.x;
    const int t = threadIdx.x;
    if (c == Csz) {
        for (int i = t; i < 768; i += TB) Cm[i] = (double)bias[i];
        __syncthreads();
        gram16d(Cm, W, 48);
        for (int i = t; i < 256; i += TB) {
            int r = i >> 4, cc = i & 15;
            W[i] = 0.25 * W[i] + ((r == cc) ? 1.0 : 0.0);
        }
        __syncthreads();
        invert16d(W, aug, M1, fs, &piv);
        for (int i = t; i < 256; i += TB) gGinvBF[i] = (float)M1[i];
        return;
    }
    const float4* gX4 = (const float4*)gXlog;
    for (int i4 = t; i4 < 256; i4 += TB) {
        float a0 = 0.f, a1 = 0.f, a2 = 0.f, a3 = 0.f;
        #pragma unroll 4
        for (int b = 0; b < Bsz; ++b) {
            float4 v = gX4[((size_t)b * Csz + c) * 256 + i4];
            a0 += v.x; a1 += v.y; a2 += v.z; a3 += v.w;
        }
        const double inv = 1.0 / (double)Bsz;
        int i = i4 * 4;
        Dm[i] = (double)a0 * inv; Dm[i + 1] = (double)a1 * inv;
        Dm[i + 2] = (double)a2 * inv; Dm[i + 3] = (double)a3 * inv;
    }
    for (int i = t; i < 1024; i += TB)
        U0[i] = (double)X[(size_t)c * 1024 + i];
    __syncthreads();
    gram16d(Dm, W, 64);
    jacobi16d(W, V, cs);
    if (t < 16) {
        double S = sqrt(fmax(W[t * 17], 0.0));
        g[t] = cos(S);
        g[16 + t] = (S > 1e-100) ? sin(S) / S : 1.0;
    }
    __syncthreads();
    vdvtd(V, g, M1);
    vdvtd(V, g + 16, M2);
    for (int i = t; i < 1024; i += TB) {
        int r = i >> 4, cc = i & 15;
        double acc = 0.0;
        #pragma unroll
        for (int x = 0; x < 16; ++x)
            acc += U0[r * 16 + x] * M1[x * 16 + cc] + Dm[r * 16 + x] * M2[x * 16 + cc];
        meanS[i] = acc;
        meanOut[c * 1024 + i] = (float)acc;
    }
    __syncthreads();
    invert16d(meanS, aug, M1, fs, &piv);
    matmul16d(meanS + 256, M1, Cm, 48);
    gram16d(Cm, W, 48);
    jacobi16d(W, V, cs);
    if (t < 16) {
        double S = sqrt(fmax(W[t * 17], 0.0));
        g[t] = (S > 1e-100) ? atan(S) / S : 1.0;
    }
    __syncthreads();
    vdvtd(V, g, M2);
    matmul16d(Cm, M2, Dm, 48);
    for (int i = t; i < 768; i += TB) gBmF[c * 768 + i] = (float)Dm[i];
    __syncthreads();
    gram16d(Dm, W, 48);
    for (int i = t; i < 256; i += TB) {
        int r = i >> 4, cc = i & 15;
        W[i] = 0.25 * W[i] + ((r == cc) ? 1.0 : 0.0);
    }
    __syncthreads();
    invert16d(W, aug, M1, fs, &piv);
    for (int i = t; i < 256; i += TB) gGinvCF[c * 256 + i] = (float)M1[i];
}

// K3 (warp-per-instance): theta^2 sum -> gTheta[bc]
__global__ void __launch_bounds__(TB) k3_theta(const float* __restrict__ X,
                                               const float* __restrict__ meanIn) {
    __shared__ alignas(16) float Mn[WPB][1024];
    __shared__ alignas(16) float Xb[WPB][1024];
    __shared__ float Mm[WPB][272];
    const int w = threadIdx.x >> 5, lane = threadIdx.x & 31;
    const int bc = blockIdx.x * WPB + w;
    const int c = bc & (Csz - 1);
    float* A = Mn[w];
    float* Xl = Xb[w];
    float* M = Mm[w];
    float* W = Mn[w];              // overlay (mean dead after M computed)
    const float4* Xp4 = (const float4*)(X + (size_t)bc * 1024);
    const float4* Mp4 = (const float4*)(meanIn + (size_t)c * 1024);
    float4* A4 = (float4*)A;
    float4* Xl4 = (float4*)Xl;
    for (int i = lane; i < 256; i += 32) { A4[i] = Mp4[i]; Xl4[i] = Xp4[i]; }
    __syncwarp();
    // M = mean^T X (vectorized, order preserved)
    {
        const int r = lane >> 1, ccb = (lane & 1) * 8;
        const int zoff = ccb >> 2;
        float acc0 = 0.f, acc1 = 0.f, acc2 = 0.f, acc3 = 0.f;
        float acc4 = 0.f, acc5 = 0.f, acc6 = 0.f, acc7 = 0.f;
        for (int x = 0; x < 64; ++x) {
            float u = A[x * 16 + r];
            float4 z0 = Xl4[x * 4 + zoff];
            float4 z1 = Xl4[x * 4 + zoff + 1];
            acc0 = __fmaf_rn(u, z0.x, acc0);
            acc1 = __fmaf_rn(u, z0.y, acc1);
            acc2 = __fmaf_rn(u, z0.z, acc2);
            acc3 = __fmaf_rn(u, z0.w, acc3);
            acc4 = __fmaf_rn(u, z1.x, acc4);
            acc5 = __fmaf_rn(u, z1.y, acc5);
            acc6 = __fmaf_rn(u, z1.z, acc6);
            acc7 = __fmaf_rn(u, z1.w, acc7);
        }
        float* Mr = M + r * S17 + ccb;
        Mr[0] = acc0; Mr[1] = acc1; Mr[2] = acc2; Mr[3] = acc3;
        Mr[4] = acc4; Mr[5] = acc5; Mr[6] = acc6; Mr[7] = acc7;
    }
    __syncwarp();
    for (int i = lane; i < 256; i += 32) {
        int r = i >> 4, cc = i & 15;
        float acc = 0.f;
        #pragma unroll
        for (int x = 0; x < 16; ++x) acc += M[x * S17 + r] * M[x * S17 + cc];
        W[r * S17 + cc] = acc;
    }
    __syncwarp();
    jacobi_warp(W, (float*)0, lane, SWEEPS_NV, false);
    if (lane == 0) {
        float sum = 0.f;
        for (int j2 = 0; j2 < 16; ++j2) {
            float s = sqrtf(fmaxf(W[j2 * 18], 0.f));
            s = fminf(s, 1.f);
            float th = acosf(s);
            sum += th * th;
        }
        gTheta[bc] = sum;
    }
}

// K4 (grid=Csz): per-channel factor via tree reduction only
__global__ void k4_factor(const float* __restrict__ shiftp) {
    __shared__ float red[TB];
    const int t = threadIdx.x;
    const int c = blockIdx.x;
    red[t] = gTheta[t * Csz + c] + gTheta[(t + TB) * Csz + c];
    __syncthreads();
    for (int s = TB / 2; s > 0; s >>= 1) {
        if (t < s) red[t] += red[t + s];
        __syncthreads();
    }
    if (t == 0) {
        double var = (double)red[0] * (1.0 / (double)Bsz);
        gFactorF[c] = (float)((double)shiftp[0] / sqrt(var + 1e-5));
    }
}

// K5 (warp-per-instance): center -> gyro scale -> bias
__global__ void __launch_bounds__(TB) k5_final(const float* __restrict__ X,
                                               const float* __restrict__ bias,
                                               float* __restrict__ out) {
    __shared__ alignas(16) float Xs[WPB][1024];
    __shared__ alignas(16) float Bmw[WPB][768];   // Bm -> V -> bot -> bias
    __shared__ alignas(16) float bufa[WPB][512];  // Ginv/W -> T1f,Tsf -> M2 / GinvB
    __shared__ alignas(16) float Tt[WPB][256];    // T (A) -> top -> T (C)
    __shared__ float lamK[WPB][16], sdK[WPB][16], gkK[WPB][16];
    const int w = threadIdx.x >> 5, lane = threadIdx.x & 31;
    const int bc = blockIdx.x * WPB + w;
    const int c = bc & (Csz - 1);
    float* Xw = Xs[w];
    float* Bw = Bmw[w];
    float* buf_f = bufa[w];
    float* T = Tt[w];
    {
        const float4* Xp4 = (const float4*)(X + (size_t)bc * 1024);
        const float4* Bm4 = (const float4*)(gBmF + (size_t)c * 768);
        const float4* Gi4 = (const float4*)(gGinvCF + (size_t)c * 256);
        float4* Xw4 = (float4*)Xw;
        float4* Bw4 = (float4*)Bw;
        float4* bf4 = (float4*)buf_f;
        for (int i = lane; i < 256; i += 32) Xw4[i] = Xp4[i];
        for (int i = lane; i < 192; i += 32) Bw4[i] = Bm4[i];
        for (int i = lane; i < 64; i += 32) bf4[i] = Gi4[i];
    }
    __syncwarp();
    // --- Step A: centering Cayley (vectorized 48-loop; order preserved) ---
    {
        const int r = lane >> 1, ccb = (lane & 1) * 8;
        const int zoff = ccb >> 2;
        const float4* Xl4 = (const float4*)(Xw + 256);
        float a0 = Xw[r * 16 + ccb],     a1 = Xw[r * 16 + ccb + 1];
        float a2 = Xw[r * 16 + ccb + 2], a3 = Xw[r * 16 + ccb + 3];
        float a4 = Xw[r * 16 + ccb + 4], a5 = Xw[r * 16 + ccb + 5];
        float a6 = Xw[r * 16 + ccb + 6], a7 = Xw[r * 16 + ccb + 7];
        for (int k = 0; k < 48; ++k) {
            float b = 0.5f * Bw[k * 16 + r];
            float4 z0 = Xl4[k * 4 + zoff];
            float4 z1 = Xl4[k * 4 + zoff + 1];
            a0 = __fmaf_rn(b, z0.x, a0);
            a1 = __fmaf_rn(b, z0.y, a1);
            a2 = __fmaf_rn(b, z0.z, a2);
            a3 = __fmaf_rn(b, z0.w, a3);
            a4 = __fmaf_rn(b, z1.x, a4);
            a5 = __fmaf_rn(b, z1.y, a5);
            a6 = __fmaf_rn(b, z1.z, a6);
            a7 = __fmaf_rn(b, z1.w, a7);
        }
        float4* T4w = (float4*)T;
        T4w[(r * 16 + ccb) >> 2]       = make_float4(a0, a1, a2, a3);
        T4w[((r * 16 + ccb) >> 2) + 1] = make_float4(a4, a5, a6, a7);
    }
    __syncwarp();
    {
        float yreg[8];
        #pragma unroll
        for (int ii = 0; ii < 8; ++ii) {
            int i = lane + 32 * ii, r = i >> 4, cc = i & 15;
            float acc = 0.f;
            #pragma unroll
            for (int x = 0; x < 16; ++x) acc += buf_f[r * 16 + x] * T[x * 16 + cc];
            yreg[ii] = acc;
        }
        __syncwarp();
        #pragma unroll
        for (int ii = 0; ii < 8; ++ii) T[lane + 32 * ii] = yreg[ii];
    }
    __syncwarp();
    for (int i = lane; i < 1024; i += 32) {
        if (i < 256) Xw[i] = 2.f * T[i] - Xw[i];
        else {
            int r = (i - 256) >> 4, cc = i & 15;
            float acc = Xw[i];
            #pragma unroll
            for (int x = 0; x < 16; ++x) acc -= Bw[r * 16 + x] * T[x * 16 + cc];
            Xw[i] = acc;                       // last use of Bm
        }
    }
    __syncwarp();
    // --- Step B: gyro scaling via K = Xu Xu^T ---
    float* W = buf_f;                          // Ginv dead
    float* V = Bw;                             // Bm dead; V stride-17 in Bmw[0..287]
    for (int i = lane; i < 256; i += 32) {
        int r = i >> 4, cc = i & 15;
        float acc = 0.f;
        #pragma unroll
        for (int x = 0; x < 16; ++x) acc += Xw[r * 16 + x] * Xw[cc * 16 + x];
        W[r * S17 + cc] = acc;
    }
    for (int i = lane; i < 288; i += 32) V[i] = 0.f;
    __syncwarp();
    if (lane < 16) V[lane * S17 + lane] = 1.f;
    jacobi_warp(W, V, lane, SWEEPS_W, true);
    // ---- compensated fp32 T1 (W dead) ----
    float* T1f = buf_f;          // 256
    for (int i = lane; i < 256; i += 32) {
        int r = i >> 4, cc = i & 15;
        float s = 0.f, comp = 0.f;
        #pragma unroll
        for (int x = 0; x < 16; ++x) {
            float a = Xw[x * 16 + r], b = V[x * S17 + cc];
            float p = __fmul_rn(a, b);
            float e = __fmaf_rn(a, b, -p);
            float y = p - comp;
            float t2 = s + y;
            comp = ((t2 - s) - y) - e;
            s = t2;
        }
        T1f[i] = s - comp;
    }
    __syncwarp();
    if (lane < 16) {
        float acc = 0.f;
        #pragma unroll
        for (int r = 0; r < 16; ++r) { float v = T1f[r * 16 + lane]; acc = __fmaf_rn(v, v, acc); }
        lamK[w][lane] = fmaxf(acc, 1e-30f);
    }
    __syncwarp();
    float fct = gFactorF[c];
    if (lane < 16) {
        double lam = (double)lamK[w][lane];
        double om = fmax(1.0 - lam, 0.0);
        double beta, cth;
        if (om < 1e-28) { beta = (double)fct; cth = 1.0; }
        else {
            double th = (double)fct * atan(sqrt(om / lam));
            beta = sin(th) / sqrt(om);
            cth = cos(th);
        }
        sdK[w][lane] = (float)(beta / sqrt(lam));
        gkK[w][lane] = (float)cth;
    }
    __syncwarp();
    float* Tsf = buf_f + 256;
    for (int i = lane; i < 256; i += 32) Tsf[i] = T1f[i] * sdK[w][i & 15];
    __syncwarp();
    // M2 = Ts V^T and top = V cos V^T, staged; commit M2 -> buf_f[0..255], top -> T
    {
        float m2reg[8], topreg[8];
        #pragma unroll
        for (int ii = 0; ii < 8; ++ii) {
            int i = lane + 32 * ii, r = i >> 4, cc = i & 15;
            float accm = 0.f, acct = 0.f;
            #pragma unroll
            for (int x = 0; x < 16; ++x) {
                accm += Tsf[r * 16 + x] * V[cc * S17 + x];
                acct += V[r * S17 + x] * gkK[w][x] * V[cc * S17 + x];
            }
            m2reg[ii] = accm;
            topreg[ii] = acct;
        }
        __syncwarp();
        #pragma unroll
        for (int ii = 0; ii < 8; ++ii) {
            buf_f[lane + 32 * ii] = m2reg[ii];   // M2
            T[lane + 32 * ii] = topreg[ii];      // top
        }
    }
    __syncwarp();
    // bot = Xl M2 into Bw (V dead) — vectorized: 3 chunks of 16 rows
    {
        const int rh = lane >> 1, ccb = (lane & 1) * 8;
        const int moff = ccb >> 2;
        const float4* M24 = (const float4*)buf_f;
        #pragma unroll
        for (int chunk = 0; chunk < 3; ++chunk) {
            int row = rh + (chunk << 4);
            float a0 = 0.f, a1 = 0.f, a2 = 0.f, a3 = 0.f;
            float a4 = 0.f, a5 = 0.f, a6 = 0.f, a7 = 0.f;
            #pragma unroll
            for (int x = 0; x < 16; ++x) {
                float a = Xw[256 + row * 16 + x];
                float4 m0 = M24[x * 4 + moff];
                float4 m1 = M24[x * 4 + moff + 1];
                a0 = __fmaf_rn(a, m0.x, a0);
                a1 = __fmaf_rn(a, m0.y, a1);
                a2 = __fmaf_rn(a, m0.z, a2);
                a3 = __fmaf_rn(a, m0.w, a3);
                a4 = __fmaf_rn(a, m1.x, a4);
                a5 = __fmaf_rn(a, m1.y, a5);
                a6 = __fmaf_rn(a, m1.z, a6);
                a7 = __fmaf_rn(a, m1.w, a7);
            }
            float4* Bw4w = (float4*)Bw;
            Bw4w[(row * 16 + ccb) >> 2]       = make_float4(a0, a1, a2, a3);
            Bw4w[((row * 16 + ccb) >> 2) + 1] = make_float4(a4, a5, a6, a7);
        }
    }
    __syncwarp();
    // commit: Xu=top, Xl=bot
    {
        float4* Xw4 = (float4*)Xw;
        float4* T4 = (float4*)T;
        float4* Bw4 = (float4*)Bw;
        for (int i = lane; i < 64; i += 32) Xw4[i] = T4[i];
        for (int i = lane; i < 192; i += 32) Xw4[64 + i] = Bw4[i];
    }
    __syncwarp();
    // --- Step C: bias Cayley ---
    {
        const float4* b4 = (const float4*)bias;
        const float4* g4 = (const float4*)gGinvBF;
        float4* Bw4 = (float4*)Bw;
        float4* bf4 = (float4*)buf_f;
        for (int i = lane; i < 192; i += 32) Bw4[i] = b4[i];
        for (int i = lane; i < 64; i += 32) bf4[i] = g4[i];
    }
    __syncwarp();
    {
        const int r = lane >> 1, ccb = (lane & 1) * 8;
        const int zoff = ccb >> 2;
        const float4* Xl4 = (const float4*)(Xw + 256);
        float a0 = Xw[r * 16 + ccb],     a1 = Xw[r * 16 + ccb + 1];
        float a2 = Xw[r * 16 + ccb + 2], a3 = Xw[r * 16 + ccb + 3];
        float a4 = Xw[r * 16 + ccb + 4], a5 = Xw[r * 16 + ccb + 5];
        float a6 = Xw[r * 16 + ccb + 6], a7 = Xw[r * 16 + ccb + 7];
        for (int k = 0; k < 48; ++k) {
            float b = 0.5f * Bw[k * 16 + r];
            float4 z0 = Xl4[k * 4 + zoff];
            float4 z1 = Xl4[k * 4 + zoff + 1];
            a0 = __fmaf_rn(-b, z0.x, a0);
            a1 = __fmaf_rn(-b, z0.y, a1);
            a2 = __fmaf_rn(-b, z0.z, a2);
            a3 = __fmaf_rn(-b, z0.w, a3);
            a4 = __fmaf_rn(-b, z1.x, a4);
            a5 = __fmaf_rn(-b, z1.y, a5);
            a6 = __fmaf_rn(-b, z1.z, a6);
            a7 = __fmaf_rn(-b, z1.w, a7);
        }
        float4* T4w = (float4*)T;
        T4w[(r * 16 + ccb) >> 2]       = make_float4(a0, a1, a2, a3);
        T4w[((r * 16 + ccb) >> 2) + 1] = make_float4(a4, a5, a6, a7);
    }
    __syncwarp();
    {
        float yreg[8];
        #pragma unroll
        for (int ii = 0; ii < 8; ++ii) {
            int i = lane + 32 * ii, r = i >> 4, cc = i & 15;
            float acc = 0.f;
            #pragma unroll
            for (int x = 0; x < 16; ++x) acc += buf_f[r * 16 + x] * T[x * 16 + cc];
            yreg[ii] = acc;
        }
        __syncwarp();
        #pragma unroll
        for (int ii = 0; ii < 8; ++ii) T[lane + 32 * ii] = yreg[ii];
    }
    __syncwarp();
    float4* dst4 = (float4*)(out + (size_t)bc * 1024);
    for (int i4 = lane; i4 < 64; i4 += 32) {
        float4 t4 = ((float4*)T)[i4];
        float4 x4 = ((float4*)Xw)[i4];
        dst4[i4] = make_float4(2.f * t4.x - x4.x, 2.f * t4.y - x4.y,
                               2.f * t4.z - x4.z, 2.f * t4.w - x4.w);
    }
    for (int i4 = lane; i4 < 192; i4 += 32) {
        int r = i4 >> 2, cb = (i4 & 3) * 4;
        float a0 = Xw[256 + r * 16 + cb];
        float a1 = Xw[256 + r * 16 + cb + 1];
        float a2 = Xw[256 + r * 16 + cb + 2];
        float a3 = Xw[256 + r * 16 + cb + 3];
        #pragma unroll
        for (int x = 0; x < 16; ++x) {
            float bv = Bw[r * 16 + x];
            a0 += bv * T[x * 16 + cb];
            a1 += bv * T[x * 16 + cb + 1];
            a2 += bv * T[x * 16 + cb + 2];
            a3 += bv * T[x * 16 + cb + 3];
        }
        dst4[64 + i4] = make_float4(a0, a1, a2, a3);
    }
}

// ---------------- launch ----------------
extern "C" void kernel_launch(void* const* d_in, const int* in_sizes, int n_in,
                              void* d_out, int out_size) {
    const float* X = (const float*)d_in[0];
    const float* bias = (const float*)d_in[1];
    const float* shift = (const float*)d_in[2];
    float* out = (float*)d_out;
    float* meanOut = out + (size_t)Bsz * Csz * Nsz * Psz;

    const int nInst = Bsz * Csz;
    k1_logmap<<<nInst / WPB, TB>>>(X);
    k2_mean<<<Csz + 1, TB>>>(X, meanOut, bias);
    k3_theta<<<nInst / WPB, TB>>>(X, meanOut);
    k4_factor<<<Csz, TB>>>(shift);
    k5_final<<<nInst / WPB, TB>>>(X, bias, out);
}